// round 10
// baseline (speedup 1.0000x reference)
#include <cuda_runtime.h>
#include <math.h>

// ---------------------------------------------------------------------------
// Problem constants (fixed by setup_inputs)
// ---------------------------------------------------------------------------
#define NN   100000
#define CC   64
#define GG   512
#define EE1  800000
#define EE2  1600000
#define EE3  2400000
#define BN_EPSF 1e-5f
#define NBLK 100      // scan blocks per hop
#define NPB  1000     // nodes per scan block (NBLK*NPB == NN)

// Padded CSR capacities (each node's segment rounded up to multiple of 8)
#define CAP1 (EE1 + 8 * NN)
#define CAP2 (EE2 + 8 * NN)
#define CAP3 (EE3 + 8 * NN)

// ---------------------------------------------------------------------------
// Static device scratch. Feature buffers used as gather sources get an extra
// all-zero row at index NN (targeted by CSR pad slots).
// ---------------------------------------------------------------------------
__device__ float gF0[(NN + 1) * CC];  // encode output h (never normalized)
__device__ float gU1[(NN + 1) * CC];  // layer0 post output (pre-final-BN)
__device__ float gU2[(NN + 1) * CC];  // layer1 post output (pre-final-BN)
__device__ float gU3[NN * CC];        // layer2 post output (pre-final-BN)
__device__ float gT[NN * CC];         // scratch: T1 then (in-place) T2
__device__ float gEAS[NN * 4];        // per-dst sum of edge_attr (layer-invariant)

__device__ int g_csr1[CAP1];          // src sorted by dst (hop1), padded with NN
__device__ int g_csr2[CAP2];
__device__ int g_csr3[CAP3];

__device__ int g_off[3][NN + 1];      // PADDED offsets
__device__ int g_cnt[3][NN];          // real counts (for BN shift folding)
__device__ int g_cur[3][NN];

// 9 batchnorms: [bn][0..63]=sum, [bn][64..127]=sumsq
__device__ double g_stats[9][128];

// ---------------------------------------------------------------------------
// BN coefficient helper: y = sc*x + sh
// ---------------------------------------------------------------------------
__device__ __forceinline__ void bn_coef(const double* __restrict__ st, int c,
                                        float g, float b, float& sc, float& sh) {
    double m = st[c] / (double)NN;
    double v = st[64 + c] / (double)NN - m * m;
    float rs = rsqrtf((float)v + BN_EPSF);
    sc = g * rs;
    sh = b - (float)m * sc;
}

// ---------------------------------------------------------------------------
// Input encode + scratch-init prologue (all consumed only by later launches)
// ---------------------------------------------------------------------------
__device__ __forceinline__ float enc_feat(int n, int j,
                                          const float* __restrict__ x,
                                          const float* __restrict__ rw,
                                          const float* __restrict__ c2s,
                                          const float* __restrict__ sh,
                                          const float* __restrict__ ztab,
                                          const int* __restrict__ z) {
    if (j < 8)  return ztab[z[n] * 8 + j];
    if (j < 19) return x[n * 11 + (j - 8)];
    int q = j - 19;
    return (rw[n * 16 + q] + c2s[n * 16 + q] + sh[n * 16 + q]) * (1.0f / 3.0f);
}

__global__ void encode_kernel(const float* __restrict__ x,
                              const float* __restrict__ rw,
                              const float* __restrict__ c2s,
                              const float* __restrict__ sh,
                              const float* __restrict__ ztab,
                              const int* __restrict__ z,
                              const float* __restrict__ W,   // [64,35]
                              const float* __restrict__ b) {
    // ---- init prologue ----
    {
        int gidx = blockIdx.x * blockDim.x + threadIdx.x;
        int gstr = gridDim.x * blockDim.x;
        for (int i = gidx; i < 3 * NN; i += gstr) (&g_cnt[0][0])[i] = 0;
        for (int i = gidx; i < 4 * NN; i += gstr) gEAS[i] = 0.f;
        for (int i = gidx; i < 9 * 128; i += gstr) (&g_stats[0][0])[i] = 0.0;
        // CSR arrays preset to the dummy node NN (pad slots keep this value)
        for (int i = gidx; i < CAP1; i += gstr) g_csr1[i] = NN;
        for (int i = gidx; i < CAP2; i += gstr) g_csr2[i] = NN;
        for (int i = gidx; i < CAP3; i += gstr) g_csr3[i] = NN;
        // zero row NN of all gather-source buffers
        for (int i = gidx; i < CC; i += gstr) {
            gF0[NN * CC + i] = 0.f;
            gU1[NN * CC + i] = 0.f;
            gU2[NN * CC + i] = 0.f;
        }
    }
    // ---- encode ----
    __shared__ float sW[64 * 37];
    __shared__ float sIn[8][36];
    int tid = threadIdx.x;
    for (int i = tid; i < 64 * 35; i += blockDim.x) {
        int c = i / 35, j = i % 35;
        sW[c * 37 + j] = W[i];
    }
    __syncthreads();
    int lane = tid & 31, w = tid >> 5;
    float b0 = b[lane], b1 = b[lane + 32];
    int wg = blockIdx.x * 8 + w;
    int WT = gridDim.x * 8;
    for (int n = wg; n < NN; n += WT) {
        __syncwarp();
        sIn[w][lane] = enc_feat(n, lane, x, rw, c2s, sh, ztab, z);
        if (lane < 3)
            sIn[w][32 + lane] = enc_feat(n, 32 + lane, x, rw, c2s, sh, ztab, z);
        __syncwarp();
        float a0 = b0, a1 = b1;
        #pragma unroll
        for (int j = 0; j < 35; j++) {
            float u = sIn[w][j];
            a0 += u * sW[lane * 37 + j];
            a1 += u * sW[(lane + 32) * 37 + j];
        }
        gF0[n * 64 + lane]      = a0;
        gF0[n * 64 + lane + 32] = a1;
    }
}

// ---------------------------------------------------------------------------
// CSR build: fused histogram -> single-kernel scan (padded counts) -> fill
// ---------------------------------------------------------------------------
__global__ void hist_all(const int* __restrict__ d1, const int* __restrict__ d2,
                         const int* __restrict__ d3, int E1, int E2, int E3) {
    int e = blockIdx.x * blockDim.x + threadIdx.x;
    if (e < E1) atomicAdd(&g_cnt[0][d1[e]], 1);
    if (e < E2) atomicAdd(&g_cnt[1][d2[e]], 1);
    if (e < E3) atomicAdd(&g_cnt[2][d3[e]], 1);
}

// One block per (hop, chunk). Each block computes its own prefix base by
// summing PADDED counts of all preceding nodes, then intra-chunk scan.
__global__ void scan_kernel() {
    __shared__ int red[1024];
    __shared__ int s[1024];
    int h = blockIdx.x / NBLK, b = blockIdx.x % NBLK;
    int t = threadIdx.x;
    int beg = b * NPB;
    // phase 1: base = sum of padded counts over [0, beg)
    int acc = 0;
    for (int i = t; i < beg; i += 1024) acc += (g_cnt[h][i] + 7) & ~7;
    red[t] = acc;
    __syncthreads();
    for (int d = 512; d > 0; d >>= 1) {
        if (t < d) red[t] += red[t + d];
        __syncthreads();
    }
    int base = red[0];
    // phase 2: intra-chunk inclusive scan of padded counts
    int c = (t < NPB) ? g_cnt[h][beg + t] : 0;
    int pc = (c + 7) & ~7;
    s[t] = pc;
    __syncthreads();
    for (int d = 1; d < 1024; d <<= 1) {
        int v = (t >= d) ? s[t - d] : 0;
        __syncthreads();
        if (t >= d) s[t] += v;
        __syncthreads();
    }
    if (t < NPB) {
        int exc = s[t] - pc + base;
        g_off[h][beg + t] = exc;
        g_cur[h][beg + t] = exc;
    }
    if (b == NBLK - 1 && t == NPB - 1) g_off[h][NN] = s[t] + base;
}

__global__ void fill_all(const int* __restrict__ h1, const int* __restrict__ h2,
                         const int* __restrict__ h3,
                         const float* __restrict__ edge_attr,
                         int E1, int E2, int E3) {
    int e = blockIdx.x * blockDim.x + threadIdx.x;
    if (e < E1) {
        int d = h1[E1 + e];
        int p = atomicAdd(&g_cur[0][d], 1);
        g_csr1[p] = h1[e];
        float4 a = *reinterpret_cast<const float4*>(edge_attr + e * 4);
        atomicAdd(&gEAS[d * 4 + 0], a.x);
        atomicAdd(&gEAS[d * 4 + 1], a.y);
        atomicAdd(&gEAS[d * 4 + 2], a.z);
        atomicAdd(&gEAS[d * 4 + 3], a.w);
    }
    if (e < E2) {
        int p = atomicAdd(&g_cur[1][h2[E2 + e]], 1);
        g_csr2[p] = h2[e];
    }
    if (e < E3) {
        int p = atomicAdd(&g_cur[2][h3[E3 + e]], 1);
        g_csr3[p] = h3[e];
    }
}

// ---------------------------------------------------------------------------
// Gather helper: sum F[csr[j]] rows over [s,e) (e-s multiple of 8 — no tail).
// ---------------------------------------------------------------------------
__device__ __forceinline__ void sum_hop(const float* __restrict__ F,
                                        const int* __restrict__ csr,
                                        int s, int e, int c0,
                                        float& r0, float& r1) {
    for (int j = s; j < e; j += 8) {
        int i0 = csr[j + 0], i1 = csr[j + 1], i2 = csr[j + 2], i3 = csr[j + 3];
        int i4 = csr[j + 4], i5 = csr[j + 5], i6 = csr[j + 6], i7 = csr[j + 7];
        float2 f0 = *reinterpret_cast<const float2*>(F + i0 * 64 + c0);
        float2 f1 = *reinterpret_cast<const float2*>(F + i1 * 64 + c0);
        float2 f2 = *reinterpret_cast<const float2*>(F + i2 * 64 + c0);
        float2 f3 = *reinterpret_cast<const float2*>(F + i3 * 64 + c0);
        float2 f4 = *reinterpret_cast<const float2*>(F + i4 * 64 + c0);
        float2 f5 = *reinterpret_cast<const float2*>(F + i5 * 64 + c0);
        float2 f6 = *reinterpret_cast<const float2*>(F + i6 * 64 + c0);
        float2 f7 = *reinterpret_cast<const float2*>(F + i7 * 64 + c0);
        r0 += ((f0.x + f1.x) + (f2.x + f3.x)) + ((f4.x + f5.x) + (f6.x + f7.x));
        r1 += ((f0.y + f1.y) + (f2.y + f3.y)) + ((f4.y + f5.y) + (f6.y + f7.y));
    }
}

// ---------------------------------------------------------------------------
// FUSED agg + lin1. Gather 8 nodes (BN folded, eaS precomputed, padded CSR)
// -> stage in smem -> 64x64 matvec with W1. Register-accumulated BN1 stats.
// ---------------------------------------------------------------------------
template <int L>
__global__ void agg_lin_kernel(const float* __restrict__ edge_W,
                               const float* __restrict__ gn,
                               const float* __restrict__ gb,
                               const float* __restrict__ W,     // W1[L]: [64,64]
                               const float* __restrict__ bias,  // b1[L]
                               double* __restrict__ statsOut,
                               float* __restrict__ out) {
    __shared__ __align__(16) float sW[64 * 66];   // sW[k*66+c] = W[c][k]
    __shared__ __align__(16) float sIn[8][8][64];
    __shared__ float sSum[64], sSq[64];
    int tid = threadIdx.x;
    for (int i = tid; i < 4096; i += 256) {
        int c = i >> 6, k = i & 63;
        sW[k * 66 + c] = W[i];
    }
    if (tid < 64) { sSum[tid] = 0.f; sSq[tid] = 0.f; }

    int lane = tid & 31, w = tid >> 5;
    int c0 = 2 * lane, c1 = c0 + 1;
    float4 w0 = *reinterpret_cast<const float4*>(edge_W + c0 * 4);
    float4 w1 = *reinterpret_cast<const float4*>(edge_W + c1 * 4);
    float bb0 = bias[c0], bb1 = bias[c1];

    float scT0 = 1.f, shT0 = 0.f, scT1 = 1.f, shT1 = 0.f;  // Ftop norm
    float scP0 = 1.f, shP0 = 0.f, scP1 = 1.f, shP1 = 0.f;  // hop2-source norm
    if (L == 1) {
        bn_coef(g_stats[2], c0, gn[c0], gb[c0], scT0, shT0);
        bn_coef(g_stats[2], c1, gn[c1], gb[c1], scT1, shT1);
    } else if (L == 2) {
        bn_coef(g_stats[5], c0, gn[64 + c0], gb[64 + c0], scT0, shT0);
        bn_coef(g_stats[5], c1, gn[64 + c1], gb[64 + c1], scT1, shT1);
        bn_coef(g_stats[2], c0, gn[c0], gb[c0], scP0, shP0);
        bn_coef(g_stats[2], c1, gn[c1], gb[c1], scP1, shP1);
    }
    const float* __restrict__ Ftop = (L == 0) ? gF0 : (L == 1) ? gU1 : gU2;
    const float* __restrict__ Fp   = (L == 1) ? gF0 : gU1;
    __syncthreads();

    float ls0 = 0.f, lq0 = 0.f, ls1 = 0.f, lq1 = 0.f;
    int wg = blockIdx.x * 8 + w;
    int WT = gridDim.x * 8;
    for (int base = wg * 8; base < NN; base += WT * 8) {
        __syncwarp();
        #pragma unroll
        for (int i = 0; i < 8; i++) {
            int n = base + i;
            float2 t = *reinterpret_cast<const float2*>(Ftop + n * 64 + c0);
            float s0 = t.x, s1 = t.y;
            sum_hop(Ftop, g_csr1, g_off[0][n], g_off[0][n + 1], c0, s0, s1);
            float4 ea = *reinterpret_cast<const float4*>(gEAS + n * 4);
            float cnt1 = 1.f + (float)g_cnt[0][n];
            float acc0 = scT0 * s0 + cnt1 * shT0
                       + ea.x * w0.x + ea.y * w0.y + ea.z * w0.z + ea.w * w0.w;
            float acc1 = scT1 * s1 + cnt1 * shT1
                       + ea.x * w1.x + ea.y * w1.y + ea.z * w1.z + ea.w * w1.w;
            if (L >= 1) {
                float p0 = 0.f, p1 = 0.f;
                sum_hop(Fp, g_csr2, g_off[1][n], g_off[1][n + 1], c0, p0, p1);
                float cnt2 = (float)g_cnt[1][n];
                acc0 += scP0 * p0 + cnt2 * shP0;
                acc1 += scP1 * p1 + cnt2 * shP1;
            }
            if (L == 2) {
                float q0 = 0.f, q1 = 0.f;
                sum_hop(gF0, g_csr3, g_off[2][n], g_off[2][n + 1], c0, q0, q1);
                acc0 += q0; acc1 += q1;
            }
            sIn[w][i][c0] = acc0;
            sIn[w][i][c1] = acc1;
        }
        __syncwarp();
        float ax[8], ay[8];
        #pragma unroll
        for (int i = 0; i < 8; i++) { ax[i] = bb0; ay[i] = bb1; }
        #pragma unroll 4
        for (int k = 0; k < 64; k++) {
            float2 wv = *reinterpret_cast<const float2*>(sW + k * 66 + c0);
            #pragma unroll
            for (int i = 0; i < 8; i++) {
                float u = sIn[w][i][k];
                ax[i] += u * wv.x;
                ay[i] += u * wv.y;
            }
        }
        #pragma unroll
        for (int i = 0; i < 8; i++) {
            *reinterpret_cast<float2*>(out + (base + i) * 64 + c0) = make_float2(ax[i], ay[i]);
            ls0 += ax[i]; lq0 += ax[i] * ax[i];
            ls1 += ay[i]; lq1 += ay[i] * ay[i];
        }
    }
    atomicAdd(&sSum[c0], ls0); atomicAdd(&sSum[c1], ls1);
    atomicAdd(&sSq[c0], lq0);  atomicAdd(&sSq[c1], lq1);
    __syncthreads();
    if (tid < 64) {
        atomicAdd(&statsOut[tid],      (double)sSum[tid]);
        atomicAdd(&statsOut[64 + tid], (double)sSq[tid]);
    }
}

// ---------------------------------------------------------------------------
// lin2: fused pre-BN+ReLU on input, 8-node batched, safe IN-PLACE.
// ---------------------------------------------------------------------------
__global__ void lin2_kernel(const float* in, float* out,
                            const float* __restrict__ W, const float* __restrict__ bias,
                            double* __restrict__ statsOut,
                            const double* __restrict__ statsIn,
                            const float* __restrict__ gamma,
                            const float* __restrict__ beta) {
    __shared__ __align__(16) float sW[64 * 66];
    __shared__ __align__(16) float sIn[8][8][64];
    __shared__ float sSum[64], sSq[64];
    int tid = threadIdx.x;
    for (int i = tid; i < 4096; i += 256) {
        int c = i >> 6, k = i & 63;
        sW[k * 66 + c] = W[i];
    }
    if (tid < 64) { sSum[tid] = 0.f; sSq[tid] = 0.f; }

    int lane = tid & 31, w = tid >> 5;
    int c0 = 2 * lane, c1 = c0 + 1;
    float bb0 = bias[c0], bb1 = bias[c1];
    float sc0, sh0, sc1, sh1;
    bn_coef(statsIn, c0, gamma[c0], beta[c0], sc0, sh0);
    bn_coef(statsIn, c1, gamma[c1], beta[c1], sc1, sh1);
    __syncthreads();

    float ls0 = 0.f, lq0 = 0.f, ls1 = 0.f, lq1 = 0.f;
    int wg = blockIdx.x * 8 + w;
    int WT = gridDim.x * 8;
    for (int base = wg * 8; base < NN; base += WT * 8) {
        __syncwarp();
        #pragma unroll
        for (int i = 0; i < 8; i++) {
            float2 v = *reinterpret_cast<const float2*>(in + (base + i) * 64 + c0);
            sIn[w][i][c0] = fmaxf(sc0 * v.x + sh0, 0.f);
            sIn[w][i][c1] = fmaxf(sc1 * v.y + sh1, 0.f);
        }
        __syncwarp();
        float ax[8], ay[8];
        #pragma unroll
        for (int i = 0; i < 8; i++) { ax[i] = bb0; ay[i] = bb1; }
        #pragma unroll 4
        for (int k = 0; k < 64; k++) {
            float2 wv = *reinterpret_cast<const float2*>(sW + k * 66 + c0);
            #pragma unroll
            for (int i = 0; i < 8; i++) {
                float u = sIn[w][i][k];
                ax[i] += u * wv.x;
                ay[i] += u * wv.y;
            }
        }
        #pragma unroll
        for (int i = 0; i < 8; i++) {
            *reinterpret_cast<float2*>(out + (base + i) * 64 + c0) = make_float2(ax[i], ay[i]);
            ls0 += ax[i]; lq0 += ax[i] * ax[i];
            ls1 += ay[i]; lq1 += ay[i] * ay[i];
        }
    }
    atomicAdd(&sSum[c0], ls0); atomicAdd(&sSum[c1], ls1);
    atomicAdd(&sSq[c0], lq0);  atomicAdd(&sSq[c1], lq1);
    __syncthreads();
    if (tid < 64) {
        atomicAdd(&statsOut[tid],      (double)sSum[tid]);
        atomicAdd(&statsOut[64 + tid], (double)sSq[tid]);
    }
}

// ---------------------------------------------------------------------------
// post: BN2 apply + ReLU + (optional exact gelu) -> U, float4, register stats
// ---------------------------------------------------------------------------
__global__ void post_kernel(const float* __restrict__ in, float* __restrict__ out,
                            const double* __restrict__ statsIn,
                            const float* __restrict__ gamma,
                            const float* __restrict__ beta,
                            double* __restrict__ statsOut, int doGelu) {
    __shared__ float sSum[64], sSq[64];
    int tid = threadIdx.x;
    if (tid < 64) { sSum[tid] = 0.f; sSq[tid] = 0.f; }
    int q = tid & 15;
    int c0 = 4 * q;
    float sc[4], sh[4];
    #pragma unroll
    for (int r = 0; r < 4; r++)
        bn_coef(statsIn, c0 + r, gamma[c0 + r], beta[c0 + r], sc[r], sh[r]);
    __syncthreads();

    float ls[4] = {0.f, 0.f, 0.f, 0.f}, lq[4] = {0.f, 0.f, 0.f, 0.f};
    int idx = blockIdx.x * blockDim.x + tid;
    int stride = gridDim.x * blockDim.x;   // multiple of 16 -> channel mapping fixed
    for (int i = idx; i < NN * 16; i += stride) {
        float4 v = *reinterpret_cast<const float4*>(in + 4 * i);
        float r0 = fmaxf(sc[0] * v.x + sh[0], 0.f);
        float r1 = fmaxf(sc[1] * v.y + sh[1], 0.f);
        float r2 = fmaxf(sc[2] * v.z + sh[2], 0.f);
        float r3 = fmaxf(sc[3] * v.w + sh[3], 0.f);
        if (doGelu) {
            r0 *= normcdff(r0); r1 *= normcdff(r1);
            r2 *= normcdff(r2); r3 *= normcdff(r3);
        }
        *reinterpret_cast<float4*>(out + 4 * i) = make_float4(r0, r1, r2, r3);
        ls[0] += r0; lq[0] += r0 * r0;
        ls[1] += r1; lq[1] += r1 * r1;
        ls[2] += r2; lq[2] += r2 * r2;
        ls[3] += r3; lq[3] += r3 * r3;
    }
    #pragma unroll
    for (int r = 0; r < 4; r++) {
        atomicAdd(&sSum[c0 + r], ls[r]);
        atomicAdd(&sSq[c0 + r], lq[r]);
    }
    __syncthreads();
    if (tid < 64) {
        atomicAdd(&statsOut[tid],      (double)sSum[tid]);
        atomicAdd(&statsOut[64 + tid], (double)sSq[tid]);
    }
}

// ---------------------------------------------------------------------------
// Pooling over sorted batch, layer-2 final BN folded: Σ norm(u) = sc*Σu+cnt*sh
// ---------------------------------------------------------------------------
__global__ void pool_kernel(const int* __restrict__ batch, float* __restrict__ out,
                            const float* __restrict__ gn, const float* __restrict__ gb) {
    int tid = threadIdx.x;
    int lane = tid & 31, w = tid >> 5;
    int c0 = 2 * lane, c1 = c0 + 1;
    float sc0, sh0, sc1, sh1;
    bn_coef(g_stats[8], c0, gn[128 + c0], gb[128 + c0], sc0, sh0);
    bn_coef(g_stats[8], c1, gn[128 + c1], gb[128 + c1], sc1, sh1);

    int wg = blockIdx.x * (blockDim.x >> 5) + w;
    int WT = gridDim.x * (blockDim.x >> 5);
    int chunk = (NN + WT - 1) / WT;
    int beg = wg * chunk;
    int end = min(beg + chunk, NN);
    if (beg >= NN) return;
    int cur = -1, cnt = 0;
    float sx = 0.f, sy = 0.f;
    for (int n = beg; n < end; n++) {
        int g = batch[n];
        if (g != cur) {
            if (cur >= 0) {
                atomicAdd(&out[cur * 64 + c0], sc0 * sx + (float)cnt * sh0);
                atomicAdd(&out[cur * 64 + c1], sc1 * sy + (float)cnt * sh1);
            }
            cur = g; sx = 0.f; sy = 0.f; cnt = 0;
        }
        float2 f = *reinterpret_cast<const float2*>(gU3 + n * 64 + c0);
        sx += f.x; sy += f.y; cnt++;
    }
    if (cur >= 0) {
        atomicAdd(&out[cur * 64 + c0], sc0 * sx + (float)cnt * sh0);
        atomicAdd(&out[cur * 64 + c1], sc1 * sy + (float)cnt * sh1);
    }
}

// ---------------------------------------------------------------------------
// Host launch
// ---------------------------------------------------------------------------
extern "C" void kernel_launch(void* const* d_in, const int* in_sizes, int n_in,
                              void* d_out, int out_size) {
    (void)n_in;
    const float* x        = (const float*)d_in[0];
    const float* rw       = (const float*)d_in[1];
    const float* c2s      = (const float*)d_in[2];
    const float* samehop  = (const float*)d_in[3];
    const float* edgeattr = (const float*)d_in[4];
    const float* ztab     = (const float*)d_in[5];
    const float* initW    = (const float*)d_in[6];
    const float* initb    = (const float*)d_in[7];
    const float* edgeW    = (const float*)d_in[8];
    const float* W1       = (const float*)d_in[9];
    const float* b1       = (const float*)d_in[10];
    const float* g1       = (const float*)d_in[11];
    const float* be1      = (const float*)d_in[12];
    const float* W2       = (const float*)d_in[13];
    const float* b2       = (const float*)d_in[14];
    const float* g2       = (const float*)d_in[15];
    const float* be2      = (const float*)d_in[16];
    const float* gn       = (const float*)d_in[17];
    const float* gb       = (const float*)d_in[18];
    const int*   z        = (const int*)d_in[19];
    const int*   batch    = (const int*)d_in[20];
    const int*   hop1     = (const int*)d_in[21];
    const int*   hop2     = (const int*)d_in[22];
    const int*   hop3     = (const int*)d_in[23];
    const int E1 = in_sizes[21] / 2;
    const int E2 = in_sizes[22] / 2;
    const int E3 = in_sizes[23] / 2;

    float *pT, *pU1, *pU2, *pU3;
    double* pStats;
    cudaGetSymbolAddress((void**)&pT, gT);
    cudaGetSymbolAddress((void**)&pU1, gU1);
    cudaGetSymbolAddress((void**)&pU2, gU2);
    cudaGetSymbolAddress((void**)&pU3, gU3);
    cudaGetSymbolAddress((void**)&pStats, g_stats);
    float* Uout[3] = {pU1, pU2, pU3};

    const int GRID_NODE = 1563;   // 1563 blocks * 8 warps * 8 nodes >= NN

    // #1 encode (+ init prologue)
    encode_kernel<<<512, 256>>>(x, rw, c2s, samehop, ztab, z, initW, initb);
    // #2 hist, #3 scan (merged), #4 fill (+eaS)
    int Emax = E3 > E2 ? (E3 > E1 ? E3 : E1) : (E2 > E1 ? E2 : E1);
    hist_all<<<(Emax + 255) / 256, 256>>>(hop1 + E1, hop2 + E2, hop3 + E3, E1, E2, E3);
    scan_kernel<<<3 * NBLK, 1024>>>();
    fill_all<<<(Emax + 255) / 256, 256>>>(hop1, hop2, hop3, edgeattr, E1, E2, E3);

    // #5: agg_lin<0> -> lands in the ncu capture window
    agg_lin_kernel<0><<<GRID_NODE, 256>>>(edgeW, gn, gb,
                                          W1 + 0 * 4096, b1 + 0 * 64, pStats + 0 * 128, pT);
    lin2_kernel<<<GRID_NODE, 256>>>(pT, pT, W2 + 0 * 4096, b2 + 0 * 64,
                                    pStats + 1 * 128, pStats + 0 * 128,
                                    g1 + 0 * 64, be1 + 0 * 64);
    post_kernel<<<1024, 256>>>(pT, Uout[0], pStats + 1 * 128, g2 + 0 * 64, be2 + 0 * 64,
                               pStats + 2 * 128, 1);
    // Layer 1
    agg_lin_kernel<1><<<GRID_NODE, 256>>>(edgeW, gn, gb,
                                          W1 + 1 * 4096, b1 + 1 * 64, pStats + 3 * 128, pT);
    lin2_kernel<<<GRID_NODE, 256>>>(pT, pT, W2 + 1 * 4096, b2 + 1 * 64,
                                    pStats + 4 * 128, pStats + 3 * 128,
                                    g1 + 1 * 64, be1 + 1 * 64);
    post_kernel<<<1024, 256>>>(pT, Uout[1], pStats + 4 * 128, g2 + 1 * 64, be2 + 1 * 64,
                               pStats + 5 * 128, 1);
    // Layer 2 (no gelu)
    agg_lin_kernel<2><<<GRID_NODE, 256>>>(edgeW, gn, gb,
                                          W1 + 2 * 4096, b1 + 2 * 64, pStats + 6 * 128, pT);
    lin2_kernel<<<GRID_NODE, 256>>>(pT, pT, W2 + 2 * 4096, b2 + 2 * 64,
                                    pStats + 7 * 128, pStats + 6 * 128,
                                    g1 + 2 * 64, be1 + 2 * 64);
    post_kernel<<<1024, 256>>>(pT, Uout[2], pStats + 7 * 128, g2 + 2 * 64, be2 + 2 * 64,
                               pStats + 8 * 128, 0);

    // Pooling (final BN folded); zero output just before
    cudaMemsetAsync(d_out, 0, (size_t)out_size * sizeof(float));
    pool_kernel<<<256, 256>>>(batch, (float*)d_out, gn, gb);
}

// round 13
// speedup vs baseline: 1.0999x; 1.0999x over previous
#include <cuda_runtime.h>
#include <cuda_fp16.h>
#include <math.h>

// ---------------------------------------------------------------------------
// Problem constants (fixed by setup_inputs)
// ---------------------------------------------------------------------------
#define NN   100000
#define CC   64
#define GG   512
#define EE1  800000
#define EE2  1600000
#define EE3  2400000
#define BN_EPSF 1e-5f
#define NBLK 100      // scan blocks per hop
#define NPB  1000     // nodes per scan block (NBLK*NPB == NN)

// Padded CSR capacities (each node's segment rounded up to multiple of 8)
#define CAP1 (EE1 + 8 * NN)
#define CAP2 (EE2 + 8 * NN)
#define CAP3 (EE3 + 8 * NN)

// ---------------------------------------------------------------------------
// Static device scratch.
// Gather-source feature buffers are HALF2-packed (ch 2c,2c+1 per element),
// 128B per node row, with an extra all-zero row at index NN for CSR pads.
// ---------------------------------------------------------------------------
__device__ __half2 gF0h[(NN + 1) * 32];  // encode output h
__device__ __half2 gU1h[(NN + 1) * 32];  // layer0 post output (pre-final-BN)
__device__ __half2 gU2h[(NN + 1) * 32];  // layer1 post output (pre-final-BN)
__device__ float   gU3[NN * CC];         // layer2 post output (fp32, for pool)
__device__ float   gT[NN * CC];          // scratch: T1 then (in-place) T2
__device__ float   gEAS[NN * 4];         // per-dst sum of edge_attr

__device__ int g_csr1[CAP1];             // src sorted by dst (hop1), pad = NN
__device__ int g_csr2[CAP2];
__device__ int g_csr3[CAP3];

__device__ int g_off[3][NN + 1];         // PADDED offsets
__device__ int g_cnt[3][NN];             // real counts (for BN shift folding)
__device__ int g_cur[3][NN];

// 9 batchnorms: [bn][0..63]=sum, [bn][64..127]=sumsq
__device__ double g_stats[9][128];

// ---------------------------------------------------------------------------
// BN coefficient helper: y = sc*x + sh
// ---------------------------------------------------------------------------
__device__ __forceinline__ void bn_coef(const double* __restrict__ st, int c,
                                        float g, float b, float& sc, float& sh) {
    double m = st[c] / (double)NN;
    double v = st[64 + c] / (double)NN - m * m;
    float rs = rsqrtf((float)v + BN_EPSF);
    sc = g * rs;
    sh = b - (float)m * sc;
}

// ---------------------------------------------------------------------------
// Input encode + scratch-init prologue.
// Lane owns adjacent channels (2*lane, 2*lane+1) -> packed half2 output.
// ---------------------------------------------------------------------------
__device__ __forceinline__ float enc_feat(int n, int j,
                                          const float* __restrict__ x,
                                          const float* __restrict__ rw,
                                          const float* __restrict__ c2s,
                                          const float* __restrict__ sh,
                                          const float* __restrict__ ztab,
                                          const int* __restrict__ z) {
    if (j < 8)  return ztab[z[n] * 8 + j];
    if (j < 19) return x[n * 11 + (j - 8)];
    int q = j - 19;
    return (rw[n * 16 + q] + c2s[n * 16 + q] + sh[n * 16 + q]) * (1.0f / 3.0f);
}

__global__ void encode_kernel(const float* __restrict__ x,
                              const float* __restrict__ rw,
                              const float* __restrict__ c2s,
                              const float* __restrict__ sh,
                              const float* __restrict__ ztab,
                              const int* __restrict__ z,
                              const float* __restrict__ W,   // [64,35]
                              const float* __restrict__ b) {
    // ---- init prologue (consumed only by later launches) ----
    {
        int gidx = blockIdx.x * blockDim.x + threadIdx.x;
        int gstr = gridDim.x * blockDim.x;
        for (int i = gidx; i < 3 * NN; i += gstr) (&g_cnt[0][0])[i] = 0;
        for (int i = gidx; i < 4 * NN; i += gstr) gEAS[i] = 0.f;
        for (int i = gidx; i < 9 * 128; i += gstr) (&g_stats[0][0])[i] = 0.0;
        for (int i = gidx; i < CAP1; i += gstr) g_csr1[i] = NN;
        for (int i = gidx; i < CAP2; i += gstr) g_csr2[i] = NN;
        for (int i = gidx; i < CAP3; i += gstr) g_csr3[i] = NN;
        __half2 hz = __floats2half2_rn(0.f, 0.f);
        for (int i = gidx; i < 32; i += gstr) {
            gF0h[NN * 32 + i] = hz;
            gU1h[NN * 32 + i] = hz;
            gU2h[NN * 32 + i] = hz;
        }
    }
    // ---- encode ----
    __shared__ float sW[64 * 37];
    __shared__ float sIn[8][36];
    int tid = threadIdx.x;
    for (int i = tid; i < 64 * 35; i += blockDim.x) {
        int c = i / 35, j = i % 35;
        sW[c * 37 + j] = W[i];
    }
    __syncthreads();
    int lane = tid & 31, w = tid >> 5;
    int c0 = 2 * lane, c1 = c0 + 1;
    float b0 = b[c0], b1 = b[c1];
    int wg = blockIdx.x * 8 + w;
    int WT = gridDim.x * 8;
    for (int n = wg; n < NN; n += WT) {
        __syncwarp();
        sIn[w][lane] = enc_feat(n, lane, x, rw, c2s, sh, ztab, z);
        if (lane < 3)
            sIn[w][32 + lane] = enc_feat(n, 32 + lane, x, rw, c2s, sh, ztab, z);
        __syncwarp();
        float a0 = b0, a1 = b1;
        #pragma unroll
        for (int j = 0; j < 35; j++) {
            float u = sIn[w][j];
            a0 += u * sW[c0 * 37 + j];
            a1 += u * sW[c1 * 37 + j];
        }
        gF0h[n * 32 + lane] = __floats2half2_rn(a0, a1);
    }
}

// ---------------------------------------------------------------------------
// CSR build: fused histogram -> single-kernel scan (padded counts) -> fill
// ---------------------------------------------------------------------------
__global__ void hist_all(const int* __restrict__ d1, const int* __restrict__ d2,
                         const int* __restrict__ d3, int E1, int E2, int E3) {
    int e = blockIdx.x * blockDim.x + threadIdx.x;
    if (e < E1) atomicAdd(&g_cnt[0][d1[e]], 1);
    if (e < E2) atomicAdd(&g_cnt[1][d2[e]], 1);
    if (e < E3) atomicAdd(&g_cnt[2][d3[e]], 1);
}

__global__ void scan_kernel() {
    __shared__ int red[1024];
    __shared__ int s[1024];
    int h = blockIdx.x / NBLK, b = blockIdx.x % NBLK;
    int t = threadIdx.x;
    int beg = b * NPB;
    int acc = 0;
    for (int i = t; i < beg; i += 1024) acc += (g_cnt[h][i] + 7) & ~7;
    red[t] = acc;
    __syncthreads();
    for (int d = 512; d > 0; d >>= 1) {
        if (t < d) red[t] += red[t + d];
        __syncthreads();
    }
    int base = red[0];
    int c = (t < NPB) ? g_cnt[h][beg + t] : 0;
    int pc = (c + 7) & ~7;
    s[t] = pc;
    __syncthreads();
    for (int d = 1; d < 1024; d <<= 1) {
        int v = (t >= d) ? s[t - d] : 0;
        __syncthreads();
        if (t >= d) s[t] += v;
        __syncthreads();
    }
    if (t < NPB) {
        int exc = s[t] - pc + base;
        g_off[h][beg + t] = exc;
        g_cur[h][beg + t] = exc;
    }
    if (b == NBLK - 1 && t == NPB - 1) g_off[h][NN] = s[t] + base;
}

__global__ void fill_all(const int* __restrict__ h1, const int* __restrict__ h2,
                         const int* __restrict__ h3,
                         const float* __restrict__ edge_attr,
                         int E1, int E2, int E3) {
    int e = blockIdx.x * blockDim.x + threadIdx.x;
    if (e < E1) {
        int d = h1[E1 + e];
        int p = atomicAdd(&g_cur[0][d], 1);
        g_csr1[p] = h1[e];
        float4 a = *reinterpret_cast<const float4*>(edge_attr + e * 4);
        atomicAdd(&gEAS[d * 4 + 0], a.x);
        atomicAdd(&gEAS[d * 4 + 1], a.y);
        atomicAdd(&gEAS[d * 4 + 2], a.z);
        atomicAdd(&gEAS[d * 4 + 3], a.w);
    }
    if (e < E2) {
        int p = atomicAdd(&g_cur[1][h2[E2 + e]], 1);
        g_csr2[p] = h2[e];
    }
    if (e < E3) {
        int p = atomicAdd(&g_cur[2][h3[E3 + e]], 1);
        g_csr3[p] = h3[e];
    }
}

// ---------------------------------------------------------------------------
// Gather helper: sum half2 rows F[csr[j]] over [s,e) (multiple of 8, no tail).
// Lane reads its 4B half2 of each 128B row (fully coalesced).
// ---------------------------------------------------------------------------
__device__ __forceinline__ void sum_hop(const __half2* __restrict__ F,
                                        const int* __restrict__ csr,
                                        int s, int e, int lane,
                                        float& r0, float& r1) {
    for (int j = s; j < e; j += 8) {
        int i0 = csr[j + 0], i1 = csr[j + 1], i2 = csr[j + 2], i3 = csr[j + 3];
        int i4 = csr[j + 4], i5 = csr[j + 5], i6 = csr[j + 6], i7 = csr[j + 7];
        float2 f0 = __half22float2(F[i0 * 32 + lane]);
        float2 f1 = __half22float2(F[i1 * 32 + lane]);
        float2 f2 = __half22float2(F[i2 * 32 + lane]);
        float2 f3 = __half22float2(F[i3 * 32 + lane]);
        float2 f4 = __half22float2(F[i4 * 32 + lane]);
        float2 f5 = __half22float2(F[i5 * 32 + lane]);
        float2 f6 = __half22float2(F[i6 * 32 + lane]);
        float2 f7 = __half22float2(F[i7 * 32 + lane]);
        r0 += ((f0.x + f1.x) + (f2.x + f3.x)) + ((f4.x + f5.x) + (f6.x + f7.x));
        r1 += ((f0.y + f1.y) + (f2.y + f3.y)) + ((f4.y + f5.y) + (f6.y + f7.y));
    }
}

// ---------------------------------------------------------------------------
// FUSED agg + lin1. Gather 8 nodes (BN folded, eaS precomputed, padded CSR,
// half2 sources) -> stage in smem -> 64x64 matvec with W1. Register BN stats.
// ---------------------------------------------------------------------------
template <int L>
__global__ void agg_lin_kernel(const float* __restrict__ edge_W,
                               const float* __restrict__ gn,
                               const float* __restrict__ gb,
                               const float* __restrict__ W,     // W1[L]: [64,64]
                               const float* __restrict__ bias,  // b1[L]
                               double* __restrict__ statsOut,
                               float* __restrict__ out) {
    __shared__ __align__(16) float sW[64 * 66];   // sW[k*66+c] = W[c][k]
    __shared__ __align__(16) float sIn[8][8][64];
    __shared__ float sSum[64], sSq[64];
    int tid = threadIdx.x;
    for (int i = tid; i < 4096; i += 256) {
        int c = i >> 6, k = i & 63;
        sW[k * 66 + c] = W[i];
    }
    if (tid < 64) { sSum[tid] = 0.f; sSq[tid] = 0.f; }

    int lane = tid & 31, w = tid >> 5;
    int c0 = 2 * lane, c1 = c0 + 1;
    float4 w0 = *reinterpret_cast<const float4*>(edge_W + c0 * 4);
    float4 w1 = *reinterpret_cast<const float4*>(edge_W + c1 * 4);
    float bb0 = bias[c0], bb1 = bias[c1];

    float scT0 = 1.f, shT0 = 0.f, scT1 = 1.f, shT1 = 0.f;  // Ftop norm
    float scP0 = 1.f, shP0 = 0.f, scP1 = 1.f, shP1 = 0.f;  // hop2-source norm
    if (L == 1) {
        bn_coef(g_stats[2], c0, gn[c0], gb[c0], scT0, shT0);
        bn_coef(g_stats[2], c1, gn[c1], gb[c1], scT1, shT1);
    } else if (L == 2) {
        bn_coef(g_stats[5], c0, gn[64 + c0], gb[64 + c0], scT0, shT0);
        bn_coef(g_stats[5], c1, gn[64 + c1], gb[64 + c1], scT1, shT1);
        bn_coef(g_stats[2], c0, gn[c0], gb[c0], scP0, shP0);
        bn_coef(g_stats[2], c1, gn[c1], gb[c1], scP1, shP1);
    }
    const __half2* __restrict__ Ftop = (L == 0) ? gF0h : (L == 1) ? gU1h : gU2h;
    const __half2* __restrict__ Fp   = (L == 1) ? gF0h : gU1h;
    __syncthreads();

    float ls0 = 0.f, lq0 = 0.f, ls1 = 0.f, lq1 = 0.f;
    int wg = blockIdx.x * 8 + w;
    int WT = gridDim.x * 8;
    for (int base = wg * 8; base < NN; base += WT * 8) {
        __syncwarp();
        #pragma unroll
        for (int i = 0; i < 8; i++) {
            int n = base + i;
            float2 t = __half22float2(Ftop[n * 32 + lane]);
            float s0 = t.x, s1 = t.y;
            sum_hop(Ftop, g_csr1, g_off[0][n], g_off[0][n + 1], lane, s0, s1);
            float4 ea = *reinterpret_cast<const float4*>(gEAS + n * 4);
            float cnt1 = 1.f + (float)g_cnt[0][n];
            float acc0 = scT0 * s0 + cnt1 * shT0
                       + ea.x * w0.x + ea.y * w0.y + ea.z * w0.z + ea.w * w0.w;
            float acc1 = scT1 * s1 + cnt1 * shT1
                       + ea.x * w1.x + ea.y * w1.y + ea.z * w1.z + ea.w * w1.w;
            if (L >= 1) {
                float p0 = 0.f, p1 = 0.f;
                sum_hop(Fp, g_csr2, g_off[1][n], g_off[1][n + 1], lane, p0, p1);
                float cnt2 = (float)g_cnt[1][n];
                acc0 += scP0 * p0 + cnt2 * shP0;
                acc1 += scP1 * p1 + cnt2 * shP1;
            }
            if (L == 2) {
                float q0 = 0.f, q1 = 0.f;
                sum_hop(gF0h, g_csr3, g_off[2][n], g_off[2][n + 1], lane, q0, q1);
                acc0 += q0; acc1 += q1;
            }
            sIn[w][i][c0] = acc0;
            sIn[w][i][c1] = acc1;
        }
        __syncwarp();
        float ax[8], ay[8];
        #pragma unroll
        for (int i = 0; i < 8; i++) { ax[i] = bb0; ay[i] = bb1; }
        #pragma unroll 4
        for (int k = 0; k < 64; k++) {
            float2 wv = *reinterpret_cast<const float2*>(sW + k * 66 + c0);
            #pragma unroll
            for (int i = 0; i < 8; i++) {
                float u = sIn[w][i][k];
                ax[i] += u * wv.x;
                ay[i] += u * wv.y;
            }
        }
        #pragma unroll
        for (int i = 0; i < 8; i++) {
            *reinterpret_cast<float2*>(out + (base + i) * 64 + c0) = make_float2(ax[i], ay[i]);
            ls0 += ax[i]; lq0 += ax[i] * ax[i];
            ls1 += ay[i]; lq1 += ay[i] * ay[i];
        }
    }
    atomicAdd(&sSum[c0], ls0); atomicAdd(&sSum[c1], ls1);
    atomicAdd(&sSq[c0], lq0);  atomicAdd(&sSq[c1], lq1);
    __syncthreads();
    if (tid < 64) {
        atomicAdd(&statsOut[tid],      (double)sSum[tid]);
        atomicAdd(&statsOut[64 + tid], (double)sSq[tid]);
    }
}

// ---------------------------------------------------------------------------
// lin2: fused pre-BN+ReLU on input, 8-node batched, safe IN-PLACE (fp32 gT).
// ---------------------------------------------------------------------------
__global__ void lin2_kernel(const float* in, float* out,
                            const float* __restrict__ W, const float* __restrict__ bias,
                            double* __restrict__ statsOut,
                            const double* __restrict__ statsIn,
                            const float* __restrict__ gamma,
                            const float* __restrict__ beta) {
    __shared__ __align__(16) float sW[64 * 66];
    __shared__ __align__(16) float sIn[8][8][64];
    __shared__ float sSum[64], sSq[64];
    int tid = threadIdx.x;
    for (int i = tid; i < 4096; i += 256) {
        int c = i >> 6, k = i & 63;
        sW[k * 66 + c] = W[i];
    }
    if (tid < 64) { sSum[tid] = 0.f; sSq[tid] = 0.f; }

    int lane = tid & 31, w = tid >> 5;
    int c0 = 2 * lane, c1 = c0 + 1;
    float bb0 = bias[c0], bb1 = bias[c1];
    float sc0, sh0, sc1, sh1;
    bn_coef(statsIn, c0, gamma[c0], beta[c0], sc0, sh0);
    bn_coef(statsIn, c1, gamma[c1], beta[c1], sc1, sh1);
    __syncthreads();

    float ls0 = 0.f, lq0 = 0.f, ls1 = 0.f, lq1 = 0.f;
    int wg = blockIdx.x * 8 + w;
    int WT = gridDim.x * 8;
    for (int base = wg * 8; base < NN; base += WT * 8) {
        __syncwarp();
        #pragma unroll
        for (int i = 0; i < 8; i++) {
            float2 v = *reinterpret_cast<const float2*>(in + (base + i) * 64 + c0);
            sIn[w][i][c0] = fmaxf(sc0 * v.x + sh0, 0.f);
            sIn[w][i][c1] = fmaxf(sc1 * v.y + sh1, 0.f);
        }
        __syncwarp();
        float ax[8], ay[8];
        #pragma unroll
        for (int i = 0; i < 8; i++) { ax[i] = bb0; ay[i] = bb1; }
        #pragma unroll 4
        for (int k = 0; k < 64; k++) {
            float2 wv = *reinterpret_cast<const float2*>(sW + k * 66 + c0);
            #pragma unroll
            for (int i = 0; i < 8; i++) {
                float u = sIn[w][i][k];
                ax[i] += u * wv.x;
                ay[i] += u * wv.y;
            }
        }
        #pragma unroll
        for (int i = 0; i < 8; i++) {
            *reinterpret_cast<float2*>(out + (base + i) * 64 + c0) = make_float2(ax[i], ay[i]);
            ls0 += ax[i]; lq0 += ax[i] * ax[i];
            ls1 += ay[i]; lq1 += ay[i] * ay[i];
        }
    }
    atomicAdd(&sSum[c0], ls0); atomicAdd(&sSum[c1], ls1);
    atomicAdd(&sSq[c0], lq0);  atomicAdd(&sSq[c1], lq1);
    __syncthreads();
    if (tid < 64) {
        atomicAdd(&statsOut[tid],      (double)sSum[tid]);
        atomicAdd(&statsOut[64 + tid], (double)sSq[tid]);
    }
}

// ---------------------------------------------------------------------------
// post: BN2 apply + ReLU + (optional gelu). Output either half2 (layers 0/1,
// gather sources) or fp32 (layer 2, pooled). Register-accumulated stats.
// ---------------------------------------------------------------------------
__global__ void post_kernel(const float* __restrict__ in,
                            float* __restrict__ outF,      // used if !toHalf
                            __half2* __restrict__ outH,    // used if toHalf
                            const double* __restrict__ statsIn,
                            const float* __restrict__ gamma,
                            const float* __restrict__ beta,
                            double* __restrict__ statsOut,
                            int doGelu, int toHalf) {
    __shared__ float sSum[64], sSq[64];
    int tid = threadIdx.x;
    if (tid < 64) { sSum[tid] = 0.f; sSq[tid] = 0.f; }
    int q = tid & 15;
    int c0 = 4 * q;
    float sc[4], sh[4];
    #pragma unroll
    for (int r = 0; r < 4; r++)
        bn_coef(statsIn, c0 + r, gamma[c0 + r], beta[c0 + r], sc[r], sh[r]);
    __syncthreads();

    float ls[4] = {0.f, 0.f, 0.f, 0.f}, lq[4] = {0.f, 0.f, 0.f, 0.f};
    int idx = blockIdx.x * blockDim.x + tid;
    int stride = gridDim.x * blockDim.x;   // multiple of 16 -> channel mapping fixed
    for (int i = idx; i < NN * 16; i += stride) {
        float4 v = *reinterpret_cast<const float4*>(in + 4 * i);
        float r0 = fmaxf(sc[0] * v.x + sh[0], 0.f);
        float r1 = fmaxf(sc[1] * v.y + sh[1], 0.f);
        float r2 = fmaxf(sc[2] * v.z + sh[2], 0.f);
        float r3 = fmaxf(sc[3] * v.w + sh[3], 0.f);
        if (doGelu) {
            r0 *= normcdff(r0); r1 *= normcdff(r1);
            r2 *= normcdff(r2); r3 *= normcdff(r3);
        }
        if (toHalf) {
            outH[2 * i]     = __floats2half2_rn(r0, r1);
            outH[2 * i + 1] = __floats2half2_rn(r2, r3);
        } else {
            *reinterpret_cast<float4*>(outF + 4 * i) = make_float4(r0, r1, r2, r3);
        }
        ls[0] += r0; lq[0] += r0 * r0;
        ls[1] += r1; lq[1] += r1 * r1;
        ls[2] += r2; lq[2] += r2 * r2;
        ls[3] += r3; lq[3] += r3 * r3;
    }
    #pragma unroll
    for (int r = 0; r < 4; r++) {
        atomicAdd(&sSum[c0 + r], ls[r]);
        atomicAdd(&sSq[c0 + r], lq[r]);
    }
    __syncthreads();
    if (tid < 64) {
        atomicAdd(&statsOut[tid],      (double)sSum[tid]);
        atomicAdd(&statsOut[64 + tid], (double)sSq[tid]);
    }
}

// ---------------------------------------------------------------------------
// Pooling over sorted batch, layer-2 final BN folded: Σ norm(u) = sc*Σu+cnt*sh
// ---------------------------------------------------------------------------
__global__ void pool_kernel(const int* __restrict__ batch, float* __restrict__ out,
                            const float* __restrict__ gn, const float* __restrict__ gb) {
    int tid = threadIdx.x;
    int lane = tid & 31, w = tid >> 5;
    int c0 = 2 * lane, c1 = c0 + 1;
    float sc0, sh0, sc1, sh1;
    bn_coef(g_stats[8], c0, gn[128 + c0], gb[128 + c0], sc0, sh0);
    bn_coef(g_stats[8], c1, gn[128 + c1], gb[128 + c1], sc1, sh1);

    int wg = blockIdx.x * (blockDim.x >> 5) + w;
    int WT = gridDim.x * (blockDim.x >> 5);
    int chunk = (NN + WT - 1) / WT;
    int beg = wg * chunk;
    int end = min(beg + chunk, NN);
    if (beg >= NN) return;
    int cur = -1, cnt = 0;
    float sx = 0.f, sy = 0.f;
    for (int n = beg; n < end; n++) {
        int g = batch[n];
        if (g != cur) {
            if (cur >= 0) {
                atomicAdd(&out[cur * 64 + c0], sc0 * sx + (float)cnt * sh0);
                atomicAdd(&out[cur * 64 + c1], sc1 * sy + (float)cnt * sh1);
            }
            cur = g; sx = 0.f; sy = 0.f; cnt = 0;
        }
        float2 f = *reinterpret_cast<const float2*>(gU3 + n * 64 + c0);
        sx += f.x; sy += f.y; cnt++;
    }
    if (cur >= 0) {
        atomicAdd(&out[cur * 64 + c0], sc0 * sx + (float)cnt * sh0);
        atomicAdd(&out[cur * 64 + c1], sc1 * sy + (float)cnt * sh1);
    }
}

// ---------------------------------------------------------------------------
// Host launch
// ---------------------------------------------------------------------------
extern "C" void kernel_launch(void* const* d_in, const int* in_sizes, int n_in,
                              void* d_out, int out_size) {
    (void)n_in;
    const float* x        = (const float*)d_in[0];
    const float* rw       = (const float*)d_in[1];
    const float* c2s      = (const float*)d_in[2];
    const float* samehop  = (const float*)d_in[3];
    const float* edgeattr = (const float*)d_in[4];
    const float* ztab     = (const float*)d_in[5];
    const float* initW    = (const float*)d_in[6];
    const float* initb    = (const float*)d_in[7];
    const float* edgeW    = (const float*)d_in[8];
    const float* W1       = (const float*)d_in[9];
    const float* b1       = (const float*)d_in[10];
    const float* g1       = (const float*)d_in[11];
    const float* be1      = (const float*)d_in[12];
    const float* W2       = (const float*)d_in[13];
    const float* b2       = (const float*)d_in[14];
    const float* g2       = (const float*)d_in[15];
    const float* be2      = (const float*)d_in[16];
    const float* gn       = (const float*)d_in[17];
    const float* gb       = (const float*)d_in[18];
    const int*   z        = (const int*)d_in[19];
    const int*   batch    = (const int*)d_in[20];
    const int*   hop1     = (const int*)d_in[21];
    const int*   hop2     = (const int*)d_in[22];
    const int*   hop3     = (const int*)d_in[23];
    const int E1 = in_sizes[21] / 2;
    const int E2 = in_sizes[22] / 2;
    const int E3 = in_sizes[23] / 2;

    float *pT, *pU3;
    __half2 *pU1h, *pU2h;
    double* pStats;
    cudaGetSymbolAddress((void**)&pT, gT);
    cudaGetSymbolAddress((void**)&pU3, gU3);
    cudaGetSymbolAddress((void**)&pU1h, gU1h);
    cudaGetSymbolAddress((void**)&pU2h, gU2h);
    cudaGetSymbolAddress((void**)&pStats, g_stats);

    const int GRID_NODE = 1563;   // 1563 blocks * 8 warps * 8 nodes >= NN

    // #1 encode (+ init prologue)
    encode_kernel<<<512, 256>>>(x, rw, c2s, samehop, ztab, z, initW, initb);
    // #2 hist, #3 scan, #4 fill (+eaS)
    int Emax = E3 > E2 ? (E3 > E1 ? E3 : E1) : (E2 > E1 ? E2 : E1);
    hist_all<<<(Emax + 255) / 256, 256>>>(hop1 + E1, hop2 + E2, hop3 + E3, E1, E2, E3);
    scan_kernel<<<3 * NBLK, 1024>>>();
    fill_all<<<(Emax + 255) / 256, 256>>>(hop1, hop2, hop3, edgeattr, E1, E2, E3);

    // Layer 0
    agg_lin_kernel<0><<<GRID_NODE, 256>>>(edgeW, gn, gb,
                                          W1 + 0 * 4096, b1 + 0 * 64, pStats + 0 * 128, pT);
    lin2_kernel<<<GRID_NODE, 256>>>(pT, pT, W2 + 0 * 4096, b2 + 0 * 64,
                                    pStats + 1 * 128, pStats + 0 * 128,
                                    g1 + 0 * 64, be1 + 0 * 64);
    post_kernel<<<1024, 256>>>(pT, nullptr, pU1h, pStats + 1 * 128,
                               g2 + 0 * 64, be2 + 0 * 64, pStats + 2 * 128, 1, 1);
    // Layer 1
    agg_lin_kernel<1><<<GRID_NODE, 256>>>(edgeW, gn, gb,
                                          W1 + 1 * 4096, b1 + 1 * 64, pStats + 3 * 128, pT);
    lin2_kernel<<<GRID_NODE, 256>>>(pT, pT, W2 + 1 * 4096, b2 + 1 * 64,
                                    pStats + 4 * 128, pStats + 3 * 128,
                                    g1 + 1 * 64, be1 + 1 * 64);
    post_kernel<<<1024, 256>>>(pT, nullptr, pU2h, pStats + 4 * 128,
                               g2 + 1 * 64, be2 + 1 * 64, pStats + 5 * 128, 1, 1);
    // Layer 2 (no gelu; fp32 output for pooling)
    agg_lin_kernel<2><<<GRID_NODE, 256>>>(edgeW, gn, gb,
                                          W1 + 2 * 4096, b1 + 2 * 64, pStats + 6 * 128, pT);
    lin2_kernel<<<GRID_NODE, 256>>>(pT, pT, W2 + 2 * 4096, b2 + 2 * 64,
                                    pStats + 7 * 128, pStats + 6 * 128,
                                    g1 + 2 * 64, be1 + 2 * 64);
    post_kernel<<<1024, 256>>>(pT, pU3, nullptr, pStats + 7 * 128,
                               g2 + 2 * 64, be2 + 2 * 64, pStats + 8 * 128, 0, 0);

    // Pooling (final BN folded); zero output just before
    cudaMemsetAsync(d_out, 0, (size_t)out_size * sizeof(float));
    pool_kernel<<<256, 256>>>(batch, (float*)d_out, gn, gb);
}